// round 9
// baseline (speedup 1.0000x reference)
#include <cuda_runtime.h>
#include <cuda_bf16.h>
#include <math.h>

// ---------------------------------------------------------------------------
// Problem constants
// ---------------------------------------------------------------------------
#define B_     4
#define T_     1024
#define DIM_   2048
#define H_     16
#define HKV_   4
#define DH_    128
#define HID_   8192
#define M_TOK  (B_ * T_)          // 4096 rows
typedef __nv_bfloat16 bf16;

// ---------------------------------------------------------------------------
// Static device scratch (no dynamic allocation allowed)
// ---------------------------------------------------------------------------
__device__ float g_q [M_TOK * DIM_];              // Q fp32
__device__ float g_k [M_TOK * HKV_ * DH_];        // K fp32
__device__ float g_v [M_TOK * HKV_ * DH_];        // V fp32
__device__ float g_s [(size_t)B_ * H_ * T_ * T_]; // scores / probs
__device__ float g_h1f[M_TOK * HID_];             // FFN gate fp32
__device__ float g_h2f[M_TOK * HID_];             // FFN up fp32

__device__ bf16 g_ah [M_TOK * DIM_];              // normed act hi/lo
__device__ bf16 g_al [M_TOK * DIM_];
__device__ bf16 g_yh [M_TOK * DIM_];              // attn out hi/lo
__device__ bf16 g_yl [M_TOK * DIM_];
__device__ bf16 g_hh [M_TOK * HID_];              // silu(h1)*h2 hi/lo
__device__ bf16 g_hl [M_TOK * HID_];

// transposed bf16 weights [N,K]
__device__ bf16 g_wqkv_h[(DIM_ + 2*HKV_*DH_) * DIM_];
__device__ bf16 g_wqkv_l[(DIM_ + 2*HKV_*DH_) * DIM_];
__device__ bf16 g_wo_h [DIM_ * DIM_];
__device__ bf16 g_wo_l [DIM_ * DIM_];
__device__ bf16 g_w12_h[(size_t)2 * HID_ * DIM_];
__device__ bf16 g_w12_l[(size_t)2 * HID_ * DIM_];
__device__ bf16 g_w3_h [(size_t)DIM_ * HID_];
__device__ bf16 g_w3_l [(size_t)DIM_ * HID_];

// ---------------------------------------------------------------------------
// Small helpers
// ---------------------------------------------------------------------------
__device__ __forceinline__ unsigned smem_u32(const void* p) {
    return (unsigned)__cvta_generic_to_shared(p);
}
__device__ __forceinline__ void cp16(unsigned dst, const void* src) {
    asm volatile("cp.async.cg.shared.global [%0], [%1], 16;" :: "r"(dst), "l"(src));
}
__device__ __forceinline__ void cp_commit() { asm volatile("cp.async.commit_group;"); }
__device__ __forceinline__ void cp_wait0()  { asm volatile("cp.async.wait_group 0;"); }

__device__ __forceinline__ unsigned long long pack2(float lo, float hi) {
    unsigned long long r;
    asm("mov.b64 %0, {%1, %2};" : "=l"(r) : "f"(lo), "f"(hi));
    return r;
}
__device__ __forceinline__ void unpack2(unsigned long long p, float& lo, float& hi) {
    asm("mov.b64 {%0, %1}, %2;" : "=f"(lo), "=f"(hi) : "l"(p));
}
__device__ __forceinline__ void fma2(unsigned long long& d,
                                     unsigned long long a, unsigned long long b) {
    asm("fma.rn.f32x2 %0, %1, %2, %0;" : "+l"(d) : "l"(a), "l"(b));
}

// mma.sync m16n8k16 bf16 (supported on plain compute_103 virtual arch)
__device__ __forceinline__ void mma16816(float* c, const unsigned* a, const unsigned* b) {
    asm volatile(
        "mma.sync.aligned.m16n8k16.row.col.f32.bf16.bf16.f32 "
        "{%0,%1,%2,%3}, {%4,%5,%6,%7}, {%8,%9}, {%0,%1,%2,%3};"
        : "+f"(c[0]), "+f"(c[1]), "+f"(c[2]), "+f"(c[3])
        : "r"(a[0]), "r"(a[1]), "r"(a[2]), "r"(a[3]), "r"(b[0]), "r"(b[1]));
}
__device__ __forceinline__ void ldsm4(unsigned* r, unsigned addr) {
    asm volatile("ldmatrix.sync.aligned.m8n8.x4.shared.b16 {%0,%1,%2,%3}, [%4];"
                 : "=r"(r[0]), "=r"(r[1]), "=r"(r[2]), "=r"(r[3]) : "r"(addr));
}

__device__ __forceinline__ void split_bf16(float v, bf16& hi, bf16& lo) {
    hi = __float2bfloat16(v);
    lo = __float2bfloat16(v - __bfloat162float(hi));
}

// ---------------------------------------------------------------------------
// Weight convert + transpose: src [Kd, Nd] fp32 -> dst_hi/lo [Nd, Kd] bf16
// ---------------------------------------------------------------------------
__global__ void __launch_bounds__(256) wsplit_t(
    const float* __restrict__ src, bf16* __restrict__ dh, bf16* __restrict__ dl,
    int Kd, int Nd, int row_off)
{
    __shared__ float tile[32][33];
    int tx = threadIdx.x, ty = threadIdx.y;          // (32, 8)
    int bx = blockIdx.x * 32;                        // N dim
    int by = blockIdx.y * 32;                        // K dim
    #pragma unroll
    for (int j = 0; j < 4; j++)
        tile[ty + 8*j][tx] = src[(size_t)(by + ty + 8*j) * Nd + bx + tx];
    __syncthreads();
    #pragma unroll
    for (int j = 0; j < 4; j++) {
        float v = tile[tx][ty + 8*j];
        bf16 hi, lo; split_bf16(v, hi, lo);
        size_t o = (size_t)(row_off + bx + ty + 8*j) * Kd + by + tx;
        dh[o] = hi; dl[o] = lo;
    }
}

// ---------------------------------------------------------------------------
// RMSNorm + bf16 hi/lo split: one block per row of 2048
// ---------------------------------------------------------------------------
__global__ void __launch_bounds__(256) rmsnorm_split(
    const float* __restrict__ x, const float* __restrict__ w,
    bf16* __restrict__ oh, bf16* __restrict__ ol)
{
    int row = blockIdx.x;
    const float4* xr = (const float4*)(x + (size_t)row * DIM_);
    const float4* wr = (const float4*)w;
    int tid = threadIdx.x;

    float4 v0 = xr[tid];
    float4 v1 = xr[tid + 256];
    float ss = v0.x*v0.x + v0.y*v0.y + v0.z*v0.z + v0.w*v0.w
             + v1.x*v1.x + v1.y*v1.y + v1.z*v1.z + v1.w*v1.w;

    #pragma unroll
    for (int o = 16; o > 0; o >>= 1) ss += __shfl_xor_sync(0xFFFFFFFFu, ss, o);
    __shared__ float red[8];
    if ((tid & 31) == 0) red[tid >> 5] = ss;
    __syncthreads();
    if (tid < 32) {
        float t = (tid < 8) ? red[tid] : 0.0f;
        #pragma unroll
        for (int o = 4; o > 0; o >>= 1) t += __shfl_xor_sync(0xFFFFFFFFu, t, o);
        if (tid == 0) red[0] = t;
    }
    __syncthreads();
    float scale = rsqrtf(red[0] * (1.0f / DIM_) + 1e-5f);

    float4 w0 = wr[tid];
    float4 w1 = wr[tid + 256];
    float vals[8] = { v0.x*scale*w0.x, v0.y*scale*w0.y, v0.z*scale*w0.z, v0.w*scale*w0.w,
                      v1.x*scale*w1.x, v1.y*scale*w1.y, v1.z*scale*w1.z, v1.w*scale*w1.w };
    size_t base = (size_t)row * DIM_;
    #pragma unroll
    for (int j = 0; j < 8; j++) {
        int col = (j < 4) ? (tid*4 + j) : (1024 + tid*4 + j - 4);
        bf16 hi, lo; split_bf16(vals[j], hi, lo);
        oh[base + col] = hi; ol[base + col] = lo;
    }
}

// ---------------------------------------------------------------------------
// HMMA bf16x3 GEMM: C[M,N] = A[M,K] * W[K,N], W stored transposed [N,K].
// CTA tile 128x128, 8 warps (2x4), warp tile 64x32, K-chunk 64, double-buffered
// cp.async. mma.sync m16n8k16 .row.col, fp32 accum, 3-term bf16 emulation.
// TCMODE 0: QKV routing. TCMODE 1: FFN12. TCMODE 2: plain (+residual).
// ---------------------------------------------------------------------------
#define KC      64
#define TSTRIDE 72                     // smem row stride in bf16 (144 B)
#define TILE_B  (128 * TSTRIDE * 2)    // 18432 B per tile
#define BUF_B   (4 * TILE_B)           // Ah, Al, Bh, Bl
#define TC_SMEM_BYTES (2 * BUF_B)      // 147456 B

template <int TCMODE>
__global__ void __launch_bounds__(256) tc_gemm(
    const bf16* __restrict__ Ah, const bf16* __restrict__ Al,
    const bf16* __restrict__ Bh, const bf16* __restrict__ Bl,
    float* __restrict__ C0, float* __restrict__ C1, float* __restrict__ C2c,
    const float* __restrict__ R, int K)
{
    extern __shared__ char smem[];
    unsigned sbase = smem_u32(smem);

    int m0  = blockIdx.y * 128;
    int n0g = blockIdx.x * 128;

    float* Cp; int ldc; int n0;
    if (TCMODE == 0) {
        if (n0g < 2048)      { Cp = C0;  ldc = DIM_; n0 = n0g; }
        else if (n0g < 2560) { Cp = C1;  ldc = 512;  n0 = n0g - 2048; }
        else                 { Cp = C2c; ldc = 512;  n0 = n0g - 2560; }
    } else if (TCMODE == 1) {
        if (n0g < HID_) { Cp = C0; ldc = HID_; n0 = n0g; }
        else            { Cp = C1; ldc = HID_; n0 = n0g - HID_; }
    } else {
        Cp = C0; ldc = gridDim.x * 128; n0 = n0g;
    }

    int tid  = threadIdx.x;
    int wid  = tid >> 5;
    int lane = tid & 31;
    int warp_m = (wid >> 2) * 64;      // 0 / 64
    int warp_n = (wid & 3) * 32;       // 0,32,64,96

    // cp.async mapping: per tile, 128 rows x 8 x 16B units = 1024 units;
    // thread covers units {tid, tid+256, tid+512, tid+768} (coalesced).
    // smem off = row*144 + col*16 ; global elem = row*K + c0 + col*8
    float acc[4][4][4];
    #pragma unroll
    for (int i = 0; i < 4; i++)
        #pragma unroll
        for (int j = 0; j < 4; j++)
            #pragma unroll
            for (int e = 0; e < 4; e++) acc[i][j][e] = 0.0f;

    const int nch = K / KC;

    // ---- prefetch chunk 0 into buffer 0 ----
    {
        const bf16* srcs[4] = { Ah, Al, Bh, Bl };
        #pragma unroll
        for (int t4 = 0; t4 < 4; t4++) {
            unsigned tb = 0 * BUF_B + t4 * TILE_B;
            const bf16* gsrc = srcs[t4];
            int rbase = (t4 < 2) ? m0 : n0g;
            #pragma unroll
            for (int i = 0; i < 4; i++) {
                int u = tid + 256 * i;
                int row = u >> 3, col = u & 7;
                cp16(sbase + tb + row * 144 + col * 16,
                     gsrc + (size_t)(rbase + row) * K + col * 8);
            }
        }
        cp_commit();
        cp_wait0();
    }
    __syncthreads();

    int cur = 0;
    for (int c = 0; c < nch; c++) {
        bool has_next = (c + 1) < nch;
        if (has_next) {
            int nxt = cur ^ 1;
            const bf16* srcs[4] = { Ah, Al, Bh, Bl };
            int c0 = (c + 1) * KC;
            #pragma unroll
            for (int t4 = 0; t4 < 4; t4++) {
                unsigned tb = nxt * BUF_B + t4 * TILE_B;
                const bf16* gsrc = srcs[t4];
                int rbase = (t4 < 2) ? m0 : n0g;
                #pragma unroll
                for (int i = 0; i < 4; i++) {
                    int u = tid + 256 * i;
                    int row = u >> 3, col = u & 7;
                    cp16(sbase + tb + row * 144 + col * 16,
                         gsrc + (size_t)(rbase + row) * K + c0 + col * 8);
                }
            }
            cp_commit();
        }

        // ---- compute on buffer cur ----
        unsigned AHb = sbase + cur * BUF_B;
        unsigned ALb = AHb + TILE_B;
        const char* BHp = smem + cur * BUF_B + 2 * TILE_B;
        const char* BLp = smem + cur * BUF_B + 3 * TILE_B;

        int lr  = lane & 15, lc8 = lane >> 4;     // ldmatrix addressing
        int gid = lane >> 2, tig = lane & 3;      // fragment ownership

        #pragma unroll
        for (int k16 = 0; k16 < KC; k16 += 16) {
            unsigned ah[4][4], al[4][4];
            #pragma unroll
            for (int mi = 0; mi < 4; mi++) {
                unsigned off = (unsigned)((warp_m + mi*16 + lr) * 144 + (k16 + lc8*8) * 2);
                ldsm4(ah[mi], AHb + off);
                ldsm4(al[mi], ALb + off);
            }
            unsigned bh[4][2], bl[4][2];
            #pragma unroll
            for (int ni = 0; ni < 4; ni++) {
                unsigned off = (unsigned)((warp_n + ni*8 + gid) * 144 + (k16 + tig*2) * 2);
                bh[ni][0] = *(const unsigned*)(BHp + off);
                bh[ni][1] = *(const unsigned*)(BHp + off + 16);
                bl[ni][0] = *(const unsigned*)(BLp + off);
                bl[ni][1] = *(const unsigned*)(BLp + off + 16);
            }
            #pragma unroll
            for (int mi = 0; mi < 4; mi++)
                #pragma unroll
                for (int ni = 0; ni < 4; ni++) {
                    mma16816(acc[mi][ni], ah[mi], bh[ni]);
                    mma16816(acc[mi][ni], ah[mi], bl[ni]);
                    mma16816(acc[mi][ni], al[mi], bh[ni]);
                }
        }

        if (has_next) {
            cp_wait0();
            __syncthreads();
            cur ^= 1;
        }
    }

    // ---- epilogue ----
    {
        int gid = lane >> 2, tig = lane & 3;
        #pragma unroll
        for (int mi = 0; mi < 4; mi++) {
            #pragma unroll
            for (int ni = 0; ni < 4; ni++) {
                int m  = m0 + warp_m + mi*16 + gid;
                int nn = n0 + warp_n + ni*8 + tig*2;
                float* c = acc[mi][ni];
                float* p0 = Cp + (size_t)m * ldc + nn;
                float* p1 = Cp + (size_t)(m + 8) * ldc + nn;
                if (TCMODE == 2 && R != nullptr) {
                    const float* r0 = R + (size_t)m * ldc + nn;
                    const float* r1 = R + (size_t)(m + 8) * ldc + nn;
                    float2 rv0 = *(const float2*)r0;
                    float2 rv1 = *(const float2*)r1;
                    *(float2*)p0 = make_float2(c[0] + rv0.x, c[1] + rv0.y);
                    *(float2*)p1 = make_float2(c[2] + rv1.x, c[3] + rv1.y);
                } else {
                    *(float2*)p0 = make_float2(c[0], c[1]);
                    *(float2*)p1 = make_float2(c[2], c[3]);
                }
            }
        }
    }
}

// ---------------------------------------------------------------------------
// fp32 SIMT GEMM for attention (modes 1: QK^T scaled, 2: PV -> bf16 split)
// 128x128 tile, KS=16, double-buffered, f32x2 FMA.
// ---------------------------------------------------------------------------
#define TS 128
#define KS 16

template <int MODE>
__global__ void __launch_bounds__(256, 2) gemm128(
    const float* __restrict__ A, const float* __restrict__ B,
    float* __restrict__ C, bf16* __restrict__ YH, bf16* __restrict__ YL,
    int K, int lda, int ldb, int ldc)
{
    int m0 = blockIdx.y * TS;
    int n0 = blockIdx.x * TS;
    int z  = blockIdx.z;

    size_t zoff = 0;
    if (MODE == 1) {
        if (n0 > m0 + TS - 1) return;                 // fully-masked tile
        int b = z >> 4, h = z & 15, kvh = h >> 2;
        A += (size_t)b * T_ * DIM_ + h * DH_;         // Q
        B += (size_t)b * T_ * (HKV_*DH_) + kvh * DH_; // K
        C += (size_t)z * T_ * T_;                     // S
    } else {                                          // MODE 2
        int b = z >> 4, h = z & 15, kvh = h >> 2;
        A += (size_t)z * T_ * T_;                     // P
        B += (size_t)b * T_ * (HKV_*DH_) + kvh * DH_; // V
        zoff = (size_t)b * T_ * DIM_ + h * DH_;       // Y (bf16 pair)
    }

    int Keff = K;
    if (MODE == 2) Keff = min(K, m0 + TS);

    __shared__ float As[2][KS][TS + 4];
    __shared__ float Bs[2][KS][TS + 4];

    int t  = threadIdx.x;
    int ar = t >> 1;
    int ak = (t & 1) * 8;
    int bk = t >> 4;
    int bn = (t & 15) * 8;
    int ty = t >> 4, tx = t & 15;

    const float* Ap  = A + (size_t)(m0 + ar) * lda + ak;
    const float* BpT = B + (size_t)(n0 + ar) * ldb + ak;
    const float* BpN = B + (size_t)bk * ldb + n0 + bn;

    unsigned long long acc2[8][4];
    {
        unsigned long long z0 = pack2(0.0f, 0.0f);
        #pragma unroll
        for (int i = 0; i < 8; i++)
            #pragma unroll
            for (int j = 0; j < 4; j++) acc2[i][j] = z0;
    }

    {
        if (MODE != 1) {
            cp16(smem_u32(&Bs[0][bk][bn]),     BpN);
            cp16(smem_u32(&Bs[0][bk][bn + 4]), BpN + 4);
            cp_commit();
        }
        float4 av0 = *(const float4*)(Ap);
        float4 av1 = *(const float4*)(Ap + 4);
        As[0][ak+0][ar] = av0.x; As[0][ak+1][ar] = av0.y;
        As[0][ak+2][ar] = av0.z; As[0][ak+3][ar] = av0.w;
        As[0][ak+4][ar] = av1.x; As[0][ak+5][ar] = av1.y;
        As[0][ak+6][ar] = av1.z; As[0][ak+7][ar] = av1.w;
        if (MODE == 1) {
            float4 bv0 = *(const float4*)(BpT);
            float4 bv1 = *(const float4*)(BpT + 4);
            Bs[0][ak+0][ar] = bv0.x; Bs[0][ak+1][ar] = bv0.y;
            Bs[0][ak+2][ar] = bv0.z; Bs[0][ak+3][ar] = bv0.w;
            Bs[0][ak+4][ar] = bv1.x; Bs[0][ak+5][ar] = bv1.y;
            Bs[0][ak+6][ar] = bv1.z; Bs[0][ak+7][ar] = bv1.w;
        } else {
            cp_wait0();
        }
    }
    __syncthreads();

    int cur = 0;
    for (int k0 = 0; k0 < Keff; k0 += KS) {
        bool has_next = (k0 + KS) < Keff;
        int nxt = cur ^ 1;
        float4 av0, av1, bv0, bv1;
        if (has_next) {
            if (MODE == 1) {
                bv0 = *(const float4*)(BpT + k0 + KS);
                bv1 = *(const float4*)(BpT + k0 + KS + 4);
            } else {
                const float* src = BpN + (size_t)(k0 + KS) * ldb;
                cp16(smem_u32(&Bs[nxt][bk][bn]),     src);
                cp16(smem_u32(&Bs[nxt][bk][bn + 4]), src + 4);
                cp_commit();
            }
            av0 = *(const float4*)(Ap + k0 + KS);
            av1 = *(const float4*)(Ap + k0 + KS + 4);
        }

        #pragma unroll
        for (int kk = 0; kk < KS; kk++) {
            float4 a0 = *(const float4*)&As[cur][kk][ty * 8];
            float4 a1 = *(const float4*)&As[cur][kk][ty * 8 + 4];
            float4 b0 = *(const float4*)&Bs[cur][kk][tx * 8];
            float4 b1 = *(const float4*)&Bs[cur][kk][tx * 8 + 4];

            unsigned long long bp0 = pack2(b0.x, b0.y);
            unsigned long long bp1 = pack2(b0.z, b0.w);
            unsigned long long bp2 = pack2(b1.x, b1.y);
            unsigned long long bp3 = pack2(b1.z, b1.w);

            float af[8] = {a0.x, a0.y, a0.z, a0.w, a1.x, a1.y, a1.z, a1.w};
            #pragma unroll
            for (int i = 0; i < 8; i++) {
                unsigned long long ap = pack2(af[i], af[i]);
                fma2(acc2[i][0], ap, bp0);
                fma2(acc2[i][1], ap, bp1);
                fma2(acc2[i][2], ap, bp2);
                fma2(acc2[i][3], ap, bp3);
            }
        }

        if (has_next) {
            As[nxt][ak+0][ar] = av0.x; As[nxt][ak+1][ar] = av0.y;
            As[nxt][ak+2][ar] = av0.z; As[nxt][ak+3][ar] = av0.w;
            As[nxt][ak+4][ar] = av1.x; As[nxt][ak+5][ar] = av1.y;
            As[nxt][ak+6][ar] = av1.z; As[nxt][ak+7][ar] = av1.w;
            if (MODE == 1) {
                Bs[nxt][ak+0][ar] = bv0.x; Bs[nxt][ak+1][ar] = bv0.y;
                Bs[nxt][ak+2][ar] = bv0.z; Bs[nxt][ak+3][ar] = bv0.w;
                Bs[nxt][ak+4][ar] = bv1.x; Bs[nxt][ak+5][ar] = bv1.y;
                Bs[nxt][ak+6][ar] = bv1.z; Bs[nxt][ak+7][ar] = bv1.w;
            } else {
                cp_wait0();
            }
            __syncthreads();
            cur = nxt;
        }
    }

    #pragma unroll
    for (int i = 0; i < 8; i++) {
        int rrow = m0 + ty * 8 + i;
        float cv[8];
        unpack2(acc2[i][0], cv[0], cv[1]);
        unpack2(acc2[i][1], cv[2], cv[3]);
        unpack2(acc2[i][2], cv[4], cv[5]);
        unpack2(acc2[i][3], cv[6], cv[7]);
        if (MODE == 1) {
            const float sc = 0.08838834764831845f;   // 1/sqrt(128)
            #pragma unroll
            for (int j = 0; j < 8; j++) cv[j] *= sc;
            #pragma unroll
            for (int j = 0; j < 8; j += 4) {
                int col = n0 + tx * 8 + j;
                *(float4*)(C + (size_t)rrow * ldc + col) =
                    make_float4(cv[j], cv[j+1], cv[j+2], cv[j+3]);
            }
        } else {
            #pragma unroll
            for (int j = 0; j < 8; j++) {
                int col = n0 + tx * 8 + j;
                size_t o = zoff + (size_t)rrow * DIM_ + col;
                bf16 hi, lo; split_bf16(cv[j], hi, lo);
                YH[o] = hi; YL[o] = lo;
            }
        }
    }
}

// ---------------------------------------------------------------------------
// RoPE (in place). layout: (4096 rows, heads*128); halves [0:64) / [64:128)
// ---------------------------------------------------------------------------
__global__ void rope_kernel(float* __restrict__ q, int heads, int total)
{
    int i = blockIdx.x * blockDim.x + threadIdx.x;
    if (i >= total) return;
    int d   = i & 63;
    int hh  = (i >> 6) % heads;
    int row = i / (heads * 64);
    int t   = row & (T_ - 1);

    float inv = powf(10000.0f, -(float)d * (1.0f / 64.0f));
    float ang = (float)t * inv;
    float s = sinf(ang), c = cosf(ang);

    float* p = q + (size_t)row * (heads * DH_) + hh * DH_ + d;
    float x1 = p[0], x2 = p[64];
    p[0]  = x1 * c - x2 * s;
    p[64] = x1 * s + x2 * c;
}

// ---------------------------------------------------------------------------
// Causal softmax over pre-scaled scores. One block per (z, t) row.
// ---------------------------------------------------------------------------
__global__ void __launch_bounds__(128) softmax_causal(float* __restrict__ S)
{
    int r = blockIdx.x;
    int z = r >> 10;
    int t = r & (T_ - 1);
    float* row = S + (size_t)z * T_ * T_ + (size_t)t * T_;
    int n = t + 1;
    int tid = threadIdx.x;

    __shared__ float red[4];

    float m = -INFINITY;
    for (int j = tid; j < n; j += 128) m = fmaxf(m, row[j]);
    #pragma unroll
    for (int o = 16; o > 0; o >>= 1) m = fmaxf(m, __shfl_xor_sync(0xFFFFFFFFu, m, o));
    if ((tid & 31) == 0) red[tid >> 5] = m;
    __syncthreads();
    m = fmaxf(fmaxf(red[0], red[1]), fmaxf(red[2], red[3]));
    __syncthreads();

    float s = 0.0f;
    for (int j = tid; j < n; j += 128) {
        float e = __expf(row[j] - m);
        row[j] = e;
        s += e;
    }
    #pragma unroll
    for (int o = 16; o > 0; o >>= 1) s += __shfl_xor_sync(0xFFFFFFFFu, s, o);
    if ((tid & 31) == 0) red[tid >> 5] = s;
    __syncthreads();
    s = red[0] + red[1] + red[2] + red[3];
    float inv = 1.0f / s;

    for (int j = tid; j < n; j += 128) row[j] *= inv;
    for (int j = n + tid; j < T_; j += 128) row[j] = 0.0f;
}

// ---------------------------------------------------------------------------
// SwiGLU + bf16 split: hh/hl = split(silu(h1f) * h2f)
// ---------------------------------------------------------------------------
__global__ void silu_mul_split(const float* __restrict__ h1,
                               const float* __restrict__ h2,
                               bf16* __restrict__ oh, bf16* __restrict__ ol, int n4)
{
    int i = blockIdx.x * blockDim.x + threadIdx.x;
    if (i >= n4) return;
    float4 a = ((const float4*)h1)[i];
    float4 b = ((const float4*)h2)[i];
    float r[4];
    r[0] = a.x / (1.0f + __expf(-a.x)) * b.x;
    r[1] = a.y / (1.0f + __expf(-a.y)) * b.y;
    r[2] = a.z / (1.0f + __expf(-a.z)) * b.z;
    r[3] = a.w / (1.0f + __expf(-a.w)) * b.w;
    #pragma unroll
    for (int j = 0; j < 4; j++) {
        bf16 hi, lo; split_bf16(r[j], hi, lo);
        oh[i*4 + j] = hi; ol[i*4 + j] = lo;
    }
}

// ---------------------------------------------------------------------------
// Launch
// ---------------------------------------------------------------------------
extern "C" void kernel_launch(void* const* d_in, const int* in_sizes, int n_in,
                              void* d_out, int out_size)
{
    const float* x      = (const float*)d_in[0];
    const float* attn_w = (const float*)d_in[1];
    const float* ff_w   = (const float*)d_in[2];
    const float* wq     = (const float*)d_in[3];
    const float* wk     = (const float*)d_in[4];
    const float* wv     = (const float*)d_in[5];
    const float* wo     = (const float*)d_in[6];
    const float* w1     = (const float*)d_in[7];
    const float* w2     = (const float*)d_in[8];
    const float* w3     = (const float*)d_in[9];
    float* out = (float*)d_out;

    float *q, *k, *v, *s, *h1f, *h2f;
    bf16 *ah, *al, *yh, *yl, *hh, *hl;
    bf16 *wqkvh, *wqkvl, *woh, *wol, *w12h, *w12l, *w3h, *w3l;
    cudaGetSymbolAddress((void**)&q,   g_q);
    cudaGetSymbolAddress((void**)&k,   g_k);
    cudaGetSymbolAddress((void**)&v,   g_v);
    cudaGetSymbolAddress((void**)&s,   g_s);
    cudaGetSymbolAddress((void**)&h1f, g_h1f);
    cudaGetSymbolAddress((void**)&h2f, g_h2f);
    cudaGetSymbolAddress((void**)&ah,  g_ah);
    cudaGetSymbolAddress((void**)&al,  g_al);
    cudaGetSymbolAddress((void**)&yh,  g_yh);
    cudaGetSymbolAddress((void**)&yl,  g_yl);
    cudaGetSymbolAddress((void**)&hh,  g_hh);
    cudaGetSymbolAddress((void**)&hl,  g_hl);
    cudaGetSymbolAddress((void**)&wqkvh, g_wqkv_h);
    cudaGetSymbolAddress((void**)&wqkvl, g_wqkv_l);
    cudaGetSymbolAddress((void**)&woh,   g_wo_h);
    cudaGetSymbolAddress((void**)&wol,   g_wo_l);
    cudaGetSymbolAddress((void**)&w12h,  g_w12_h);
    cudaGetSymbolAddress((void**)&w12l,  g_w12_l);
    cudaGetSymbolAddress((void**)&w3h,   g_w3_h);
    cudaGetSymbolAddress((void**)&w3l,   g_w3_l);

    cudaFuncSetAttribute(tc_gemm<0>, cudaFuncAttributeMaxDynamicSharedMemorySize, TC_SMEM_BYTES);
    cudaFuncSetAttribute(tc_gemm<1>, cudaFuncAttributeMaxDynamicSharedMemorySize, TC_SMEM_BYTES);
    cudaFuncSetAttribute(tc_gemm<2>, cudaFuncAttributeMaxDynamicSharedMemorySize, TC_SMEM_BYTES);

    dim3 tb(32, 8);

    // ---- weight convert + transpose (every call; deterministic) ----
    wsplit_t<<<dim3(DIM_/32, DIM_/32), tb>>>(wq, wqkvh, wqkvl, DIM_, DIM_, 0);
    wsplit_t<<<dim3(512/32,  DIM_/32), tb>>>(wk, wqkvh, wqkvl, DIM_, 512,  2048);
    wsplit_t<<<dim3(512/32,  DIM_/32), tb>>>(wv, wqkvh, wqkvl, DIM_, 512,  2560);
    wsplit_t<<<dim3(DIM_/32, DIM_/32), tb>>>(wo, woh, wol, DIM_, DIM_, 0);
    wsplit_t<<<dim3(HID_/32, DIM_/32), tb>>>(w1, w12h, w12l, DIM_, HID_, 0);
    wsplit_t<<<dim3(HID_/32, DIM_/32), tb>>>(w2, w12h, w12l, DIM_, HID_, HID_);
    wsplit_t<<<dim3(DIM_/32, HID_/32), tb>>>(w3, w3h, w3l, HID_, DIM_, 0);

    // ---- attention branch ----
    rmsnorm_split<<<M_TOK, 256>>>(x, attn_w, ah, al);

    // QKV: N = 3072
    tc_gemm<0><<<dim3(3072/128, M_TOK/128), 256, TC_SMEM_BYTES>>>(
        ah, al, wqkvh, wqkvl, q, k, v, nullptr, DIM_);

    {
        int tq = M_TOK * H_ * 64;
        rope_kernel<<<(tq + 255) / 256, 256>>>(q, H_, tq);
        int tk = M_TOK * HKV_ * 64;
        rope_kernel<<<(tk + 255) / 256, 256>>>(k, HKV_, tk);
    }

    // scores + softmax + PV (fp32 SIMT; PV writes bf16 split of y)
    gemm128<1><<<dim3(T_/TS, T_/TS, B_*H_), 256>>>(q, k, s, nullptr, nullptr,
        DH_, DIM_, HKV_*DH_, T_);
    softmax_causal<<<B_*H_*T_, 128>>>(s);
    gemm128<2><<<dim3(DH_/TS, T_/TS, B_*H_), 256>>>(s, v, nullptr, yh, yl,
        T_, T_, HKV_*DH_, DIM_);

    // out = x + y @ wo
    tc_gemm<2><<<dim3(DIM_/128, M_TOK/128), 256, TC_SMEM_BYTES>>>(
        yh, yl, woh, wol, out, nullptr, nullptr, x, DIM_);

    // ---- FFN branch ----
    rmsnorm_split<<<M_TOK, 256>>>(out, ff_w, ah, al);

    tc_gemm<1><<<dim3((2*HID_)/128, M_TOK/128), 256, TC_SMEM_BYTES>>>(
        ah, al, w12h, w12l, h1f, h2f, nullptr, nullptr, DIM_);

    {
        int n4 = (M_TOK * HID_) / 4;
        silu_mul_split<<<(n4 + 255) / 256, 256>>>(h1f, h2f, hh, hl, n4);
    }

    // out = out + (silu(h1)*h2) @ w3
    tc_gemm<2><<<dim3(DIM_/128, M_TOK/128), 256, TC_SMEM_BYTES>>>(
        hh, hl, w3h, w3l, out, nullptr, nullptr, out, HID_);
}

// round 11
// speedup vs baseline: 1.0712x; 1.0712x over previous
#include <cuda_runtime.h>
#include <cuda_bf16.h>
#include <math.h>

// ---------------------------------------------------------------------------
// Problem constants
// ---------------------------------------------------------------------------
#define B_     4
#define T_     1024
#define DIM_   2048
#define H_     16
#define HKV_   4
#define DH_    128
#define HID_   8192
#define M_TOK  (B_ * T_)          // 4096 rows
typedef __nv_bfloat16 bf16;

// ---------------------------------------------------------------------------
// Static device scratch (no dynamic allocation allowed)
// ---------------------------------------------------------------------------
__device__ float g_q [M_TOK * DIM_];              // Q fp32 (pre-rope)
__device__ float g_k [M_TOK * HKV_ * DH_];        // K fp32 (pre-rope)
__device__ float g_v [M_TOK * HKV_ * DH_];        // V fp32
__device__ float g_s [(size_t)B_ * H_ * T_ * T_]; // scores fp32
__device__ float g_h1f[M_TOK * HID_];             // FFN gate fp32
__device__ float g_h2f[M_TOK * HID_];             // FFN up fp32

__device__ bf16 g_ah [M_TOK * DIM_];              // normed act hi/lo
__device__ bf16 g_al [M_TOK * DIM_];
__device__ bf16 g_qh [M_TOK * DIM_];              // roped Q hi/lo
__device__ bf16 g_ql [M_TOK * DIM_];
__device__ bf16 g_kh [M_TOK * HKV_ * DH_];        // roped K hi/lo
__device__ bf16 g_kl [M_TOK * HKV_ * DH_];
__device__ bf16 g_vth[M_TOK * HKV_ * DH_];        // V^T hi/lo  [b,kv][128][1024]
__device__ bf16 g_vtl[M_TOK * HKV_ * DH_];
__device__ bf16 g_ph [(size_t)B_ * H_ * T_ * T_]; // probs hi/lo
__device__ bf16 g_pl [(size_t)B_ * H_ * T_ * T_];
__device__ bf16 g_yh [M_TOK * DIM_];              // attn out hi/lo
__device__ bf16 g_yl [M_TOK * DIM_];
__device__ bf16 g_hh [M_TOK * HID_];              // silu(h1)*h2 hi/lo
__device__ bf16 g_hl [M_TOK * HID_];

// transposed bf16 weights [N,K]
__device__ bf16 g_wqkv_h[(DIM_ + 2*HKV_*DH_) * DIM_];
__device__ bf16 g_wqkv_l[(DIM_ + 2*HKV_*DH_) * DIM_];
__device__ bf16 g_wo_h [DIM_ * DIM_];
__device__ bf16 g_wo_l [DIM_ * DIM_];
__device__ bf16 g_w12_h[(size_t)2 * HID_ * DIM_];
__device__ bf16 g_w12_l[(size_t)2 * HID_ * DIM_];
__device__ bf16 g_w3_h [(size_t)DIM_ * HID_];
__device__ bf16 g_w3_l [(size_t)DIM_ * HID_];

// ---------------------------------------------------------------------------
// Small helpers
// ---------------------------------------------------------------------------
__device__ __forceinline__ unsigned smem_u32(const void* p) {
    return (unsigned)__cvta_generic_to_shared(p);
}
__device__ __forceinline__ void cp16(unsigned dst, const void* src) {
    asm volatile("cp.async.cg.shared.global [%0], [%1], 16;" :: "r"(dst), "l"(src));
}
__device__ __forceinline__ void cp_commit() { asm volatile("cp.async.commit_group;"); }
__device__ __forceinline__ void cp_wait0()  { asm volatile("cp.async.wait_group 0;"); }

// mma.sync m16n8k16 bf16 (plain compute_103-safe)
__device__ __forceinline__ void mma16816(float* c, const unsigned* a, const unsigned* b) {
    asm volatile(
        "mma.sync.aligned.m16n8k16.row.col.f32.bf16.bf16.f32 "
        "{%0,%1,%2,%3}, {%4,%5,%6,%7}, {%8,%9}, {%0,%1,%2,%3};"
        : "+f"(c[0]), "+f"(c[1]), "+f"(c[2]), "+f"(c[3])
        : "r"(a[0]), "r"(a[1]), "r"(a[2]), "r"(a[3]), "r"(b[0]), "r"(b[1]));
}
__device__ __forceinline__ void ldsm4(unsigned* r, unsigned addr) {
    asm volatile("ldmatrix.sync.aligned.m8n8.x4.shared.b16 {%0,%1,%2,%3}, [%4];"
                 : "=r"(r[0]), "=r"(r[1]), "=r"(r[2]), "=r"(r[3]) : "r"(addr));
}

__device__ __forceinline__ void split_bf16(float v, bf16& hi, bf16& lo) {
    hi = __float2bfloat16(v);
    lo = __float2bfloat16(v - __bfloat162float(hi));
}

// ---------------------------------------------------------------------------
// Weight convert + transpose: src [Kd, Nd] fp32 -> dst_hi/lo [Nd, Kd] bf16
// ---------------------------------------------------------------------------
__global__ void __launch_bounds__(256) wsplit_t(
    const float* __restrict__ src, bf16* __restrict__ dh, bf16* __restrict__ dl,
    int Kd, int Nd, int row_off)
{
    __shared__ float tile[32][33];
    int tx = threadIdx.x, ty = threadIdx.y;          // (32, 8)
    int bx = blockIdx.x * 32;                        // N dim
    int by = blockIdx.y * 32;                        // K dim
    #pragma unroll
    for (int j = 0; j < 4; j++)
        tile[ty + 8*j][tx] = src[(size_t)(by + ty + 8*j) * Nd + bx + tx];
    __syncthreads();
    #pragma unroll
    for (int j = 0; j < 4; j++) {
        float v = tile[tx][ty + 8*j];
        bf16 hi, lo; split_bf16(v, hi, lo);
        size_t o = (size_t)(row_off + bx + ty + 8*j) * Kd + by + tx;
        dh[o] = hi; dl[o] = lo;
    }
}

// ---------------------------------------------------------------------------
// V transpose + split: v fp32 [4096, 512] -> vt hi/lo [(b*4+kv)*128 + d][1024]
// grid (4, 32, 16) block (32, 8)
// ---------------------------------------------------------------------------
__global__ void __launch_bounds__(256) vsplit_t(
    const float* __restrict__ v, bf16* __restrict__ dh, bf16* __restrict__ dl)
{
    __shared__ float tile[32][33];
    int tx = threadIdx.x, ty = threadIdx.y;
    int z = blockIdx.z;                 // b*4 + kv
    int b = z >> 2, kv = z & 3;
    int sx = blockIdx.x * 32;           // d
    int sy = blockIdx.y * 32;           // s
    #pragma unroll
    for (int j = 0; j < 4; j++)
        tile[ty + 8*j][tx] =
            v[(size_t)(b*T_ + sy + ty + 8*j) * (HKV_*DH_) + kv*DH_ + sx + tx];
    __syncthreads();
    #pragma unroll
    for (int j = 0; j < 4; j++) {
        float val = tile[tx][ty + 8*j];
        bf16 hi, lo; split_bf16(val, hi, lo);
        size_t o = ((size_t)z*DH_ + sx + ty + 8*j) * T_ + sy + tx;
        dh[o] = hi; dl[o] = lo;
    }
}

// ---------------------------------------------------------------------------
// RMSNorm + bf16 hi/lo split: one block per row of 2048
// ---------------------------------------------------------------------------
__global__ void __launch_bounds__(256) rmsnorm_split(
    const float* __restrict__ x, const float* __restrict__ w,
    bf16* __restrict__ oh, bf16* __restrict__ ol)
{
    int row = blockIdx.x;
    const float4* xr = (const float4*)(x + (size_t)row * DIM_);
    const float4* wr = (const float4*)w;
    int tid = threadIdx.x;

    float4 v0 = xr[tid];
    float4 v1 = xr[tid + 256];
    float ss = v0.x*v0.x + v0.y*v0.y + v0.z*v0.z + v0.w*v0.w
             + v1.x*v1.x + v1.y*v1.y + v1.z*v1.z + v1.w*v1.w;

    #pragma unroll
    for (int o = 16; o > 0; o >>= 1) ss += __shfl_xor_sync(0xFFFFFFFFu, ss, o);
    __shared__ float red[8];
    if ((tid & 31) == 0) red[tid >> 5] = ss;
    __syncthreads();
    if (tid < 32) {
        float t = (tid < 8) ? red[tid] : 0.0f;
        #pragma unroll
        for (int o = 4; o > 0; o >>= 1) t += __shfl_xor_sync(0xFFFFFFFFu, t, o);
        if (tid == 0) red[0] = t;
    }
    __syncthreads();
    float scale = rsqrtf(red[0] * (1.0f / DIM_) + 1e-5f);

    float4 w0 = wr[tid];
    float4 w1 = wr[tid + 256];
    float vals[8] = { v0.x*scale*w0.x, v0.y*scale*w0.y, v0.z*scale*w0.z, v0.w*scale*w0.w,
                      v1.x*scale*w1.x, v1.y*scale*w1.y, v1.z*scale*w1.z, v1.w*scale*w1.w };
    size_t base = (size_t)row * DIM_;
    #pragma unroll
    for (int j = 0; j < 8; j++) {
        int col = (j < 4) ? (tid*4 + j) : (1024 + tid*4 + j - 4);
        bf16 hi, lo; split_bf16(vals[j], hi, lo);
        oh[base + col] = hi; ol[base + col] = lo;
    }
}

// ---------------------------------------------------------------------------
// RoPE + split: read fp32, rotate, write bf16 hi/lo
// ---------------------------------------------------------------------------
__global__ void rope_split(const float* __restrict__ src,
                           bf16* __restrict__ oh, bf16* __restrict__ ol,
                           int heads, int total)
{
    int i = blockIdx.x * blockDim.x + threadIdx.x;
    if (i >= total) return;
    int d   = i & 63;
    int hh  = (i >> 6) % heads;
    int row = i / (heads * 64);
    int t   = row & (T_ - 1);

    float inv = powf(10000.0f, -(float)d * (1.0f / 64.0f));
    float ang = (float)t * inv;
    float s = sinf(ang), c = cosf(ang);

    size_t p = (size_t)row * (heads * DH_) + hh * DH_ + d;
    float x1 = src[p], x2 = src[p + 64];
    float y1 = x1 * c - x2 * s;
    float y2 = x1 * s + x2 * c;
    bf16 h1, l1, h2, l2;
    split_bf16(y1, h1, l1);
    split_bf16(y2, h2, l2);
    oh[p] = h1;      ol[p] = l1;
    oh[p + 64] = h2; ol[p + 64] = l2;
}

// ---------------------------------------------------------------------------
// Single-pass causal softmax: read fp32 scores row, write bf16 hi/lo probs.
// One block (128 thr) per (z, t) row; row length T_=1024 in registers.
// ---------------------------------------------------------------------------
__global__ void __launch_bounds__(128) softmax_split(
    const float* __restrict__ S, bf16* __restrict__ PH, bf16* __restrict__ PL)
{
    int r = blockIdx.x;
    int z = r >> 10;
    int t = r & (T_ - 1);
    const float* row = S + (size_t)z * T_ * T_ + (size_t)t * T_;
    int tid = threadIdx.x;

    __shared__ float red[4];

    float v[8];
    float m = -INFINITY;
    #pragma unroll
    for (int i = 0; i < 8; i++) {
        int j = tid + 128 * i;
        v[i] = (j <= t) ? row[j] : -INFINITY;
        m = fmaxf(m, v[i]);
    }
    #pragma unroll
    for (int o = 16; o > 0; o >>= 1) m = fmaxf(m, __shfl_xor_sync(0xFFFFFFFFu, m, o));
    if ((tid & 31) == 0) red[tid >> 5] = m;
    __syncthreads();
    m = fmaxf(fmaxf(red[0], red[1]), fmaxf(red[2], red[3]));
    __syncthreads();

    float ssum = 0.0f;
    #pragma unroll
    for (int i = 0; i < 8; i++) {
        int j = tid + 128 * i;
        float e = (j <= t) ? __expf(v[i] - m) : 0.0f;
        v[i] = e;
        ssum += e;
    }
    #pragma unroll
    for (int o = 16; o > 0; o >>= 1) ssum += __shfl_xor_sync(0xFFFFFFFFu, ssum, o);
    if ((tid & 31) == 0) red[tid >> 5] = ssum;
    __syncthreads();
    ssum = red[0] + red[1] + red[2] + red[3];
    float inv = 1.0f / ssum;

    size_t base = (size_t)z * T_ * T_ + (size_t)t * T_;
    #pragma unroll
    for (int i = 0; i < 8; i++) {
        int j = tid + 128 * i;
        bf16 hi, lo; split_bf16(v[i] * inv, hi, lo);
        PH[base + j] = hi;
        PL[base + j] = lo;
    }
}

// ---------------------------------------------------------------------------
// HMMA bf16x3 GEMM. CTA 128x128, 8 warps (2x4), warp 64x32, K-chunk 64,
// double-buffered cp.async, mma.sync m16n8k16 .row.col, fp32 accum.
// TCMODE 0: QKV routing. TCMODE 1: FFN12. TCMODE 2: plain (+residual).
// TCMODE 3: scores  S[z] = (Q K^T)/sqrt(DH), causal tile skip.
// TCMODE 4: PV      Y[z] = P V  (A=probs, B=V^T), causal K truncation,
//                   output written as bf16 hi/lo split.
// ---------------------------------------------------------------------------
#define KC      64
#define TILE_B  (128 * 72 * 2)         // 18432 B per tile (144 B row stride)
#define BUF_B   (4 * TILE_B)
#define TC_SMEM_BYTES (2 * BUF_B)      // 147456 B

template <int TCMODE>
__global__ void __launch_bounds__(256) tc_gemm(
    const bf16* __restrict__ Ah, const bf16* __restrict__ Al,
    const bf16* __restrict__ Bh, const bf16* __restrict__ Bl,
    float* __restrict__ C0, float* __restrict__ C1, float* __restrict__ C2c,
    const float* __restrict__ R,
    bf16* __restrict__ YH, bf16* __restrict__ YL, int K)
{
    extern __shared__ char smem[];
    unsigned sbase = smem_u32(smem);

    int m0  = blockIdx.y * 128;
    int n0g = blockIdx.x * 128;
    int z   = blockIdx.z;

    int lda = K, ldb = K, Keff = K;
    size_t aoff = 0, boff = 0;
    int zb = 0, zh = 0;

    if (TCMODE == 3) {
        if (n0g > m0 + 127) return;                   // fully-masked tile
        zb = z >> 4; zh = z & 15;
        int kvh = zh >> 2;
        aoff = (size_t)zb * T_ * DIM_ + zh * DH_;  lda = DIM_;
        boff = (size_t)zb * T_ * (HKV_*DH_) + kvh * DH_; ldb = HKV_*DH_;
        Keff = DH_;                                   // 128
    } else if (TCMODE == 4) {
        zb = z >> 4; zh = z & 15;
        int kvh = zh >> 2;
        aoff = (size_t)z * T_ * T_;                 lda = T_;
        boff = (size_t)(zb * HKV_ + kvh) * DH_ * T_; ldb = T_;
        Keff = m0 + 128;                              // causal truncation
    }

    float* Cp = C0; int ldc = 0; int n0 = n0g;
    if (TCMODE == 0) {
        if (n0g < 2048)      { Cp = C0;  ldc = DIM_; n0 = n0g; }
        else if (n0g < 2560) { Cp = C1;  ldc = 512;  n0 = n0g - 2048; }
        else                 { Cp = C2c; ldc = 512;  n0 = n0g - 2560; }
    } else if (TCMODE == 1) {
        if (n0g < HID_) { Cp = C0; ldc = HID_; n0 = n0g; }
        else            { Cp = C1; ldc = HID_; n0 = n0g - HID_; }
    } else if (TCMODE == 2) {
        Cp = C0; ldc = gridDim.x * 128; n0 = n0g;
    } else if (TCMODE == 3) {
        Cp = C0 + (size_t)z * T_ * T_; ldc = T_; n0 = n0g;
    }

    int tid  = threadIdx.x;
    int wid  = tid >> 5;
    int lane = tid & 31;
    int warp_m = (wid >> 2) * 64;
    int warp_n = (wid & 3) * 32;

    const bf16* pAh = Ah + aoff;
    const bf16* pAl = Al + aoff;
    const bf16* pBh = Bh + boff;
    const bf16* pBl = Bl + boff;

    float acc[4][4][4];
    #pragma unroll
    for (int i = 0; i < 4; i++)
        #pragma unroll
        for (int j = 0; j < 4; j++)
            #pragma unroll
            for (int e = 0; e < 4; e++) acc[i][j][e] = 0.0f;

    const int nch = Keff / KC;

    // ---- prefetch chunk 0 into buffer 0 ----
    {
        const bf16* srcs[4] = { pAh, pAl, pBh, pBl };
        #pragma unroll
        for (int t4 = 0; t4 < 4; t4++) {
            unsigned tb = t4 * TILE_B;
            int rbase = (t4 < 2) ? m0 : n0g;
            int ld    = (t4 < 2) ? lda : ldb;
            #pragma unroll
            for (int i = 0; i < 4; i++) {
                int u = tid + 256 * i;
                int row = u >> 3, col = u & 7;
                cp16(sbase + tb + row * 144 + col * 16,
                     srcs[t4] + (size_t)(rbase + row) * ld + col * 8);
            }
        }
        cp_commit();
        cp_wait0();
    }
    __syncthreads();

    int cur = 0;
    for (int c = 0; c < nch; c++) {
        bool has_next = (c + 1) < nch;
        if (has_next) {
            int nxt = cur ^ 1;
            const bf16* srcs[4] = { pAh, pAl, pBh, pBl };
            int c0 = (c + 1) * KC;
            #pragma unroll
            for (int t4 = 0; t4 < 4; t4++) {
                unsigned tb = nxt * BUF_B + t4 * TILE_B;
                int rbase = (t4 < 2) ? m0 : n0g;
                int ld    = (t4 < 2) ? lda : ldb;
                #pragma unroll
                for (int i = 0; i < 4; i++) {
                    int u = tid + 256 * i;
                    int row = u >> 3, col = u & 7;
                    cp16(sbase + tb + row * 144 + col * 16,
                         srcs[t4] + (size_t)(rbase + row) * ld + c0 + col * 8);
                }
            }
            cp_commit();
        }

        unsigned AHb = sbase + cur * BUF_B;
        unsigned ALb = AHb + TILE_B;
        const char* BHp = smem + cur * BUF_B + 2 * TILE_B;
        const char* BLp = smem + cur * BUF_B + 3 * TILE_B;

        int lr  = lane & 15, lc8 = lane >> 4;
        int gid = lane >> 2, tig = lane & 3;

        #pragma unroll
        for (int k16 = 0; k16 < KC; k16 += 16) {
            unsigned ah[4][4], al[4][4];
            #pragma unroll
            for (int mi = 0; mi < 4; mi++) {
                unsigned off = (unsigned)((warp_m + mi*16 + lr) * 144 + (k16 + lc8*8) * 2);
                ldsm4(ah[mi], AHb + off);
                ldsm4(al[mi], ALb + off);
            }
            unsigned bh[4][2], bl[4][2];
            #pragma unroll
            for (int ni = 0; ni < 4; ni++) {
                unsigned off = (unsigned)((warp_n + ni*8 + gid) * 144 + (k16 + tig*2) * 2);
                bh[ni][0] = *(const unsigned*)(BHp + off);
                bh[ni][1] = *(const unsigned*)(BHp + off + 16);
                bl[ni][0] = *(const unsigned*)(BLp + off);
                bl[ni][1] = *(const unsigned*)(BLp + off + 16);
            }
            #pragma unroll
            for (int mi = 0; mi < 4; mi++)
                #pragma unroll
                for (int ni = 0; ni < 4; ni++) {
                    mma16816(acc[mi][ni], ah[mi], bh[ni]);
                    mma16816(acc[mi][ni], ah[mi], bl[ni]);
                    mma16816(acc[mi][ni], al[mi], bh[ni]);
                }
        }

        if (has_next) {
            cp_wait0();
            __syncthreads();
            cur ^= 1;
        }
    }

    // ---- epilogue ----
    {
        int gid = lane >> 2, tig = lane & 3;
        #pragma unroll
        for (int mi = 0; mi < 4; mi++) {
            #pragma unroll
            for (int ni = 0; ni < 4; ni++) {
                int m  = m0 + warp_m + mi*16 + gid;
                int nn = n0 + warp_n + ni*8 + tig*2;
                float* c = acc[mi][ni];
                if (TCMODE == 4) {
                    // write bf16 split of y at (b*T + m, h*DH + nn)
                    size_t o0 = (size_t)(zb * T_ + m)     * DIM_ + zh * DH_ + nn;
                    size_t o1 = (size_t)(zb * T_ + m + 8) * DIM_ + zh * DH_ + nn;
                    bf16 h0a, l0a, h0b, l0b, h1a, l1a, h1b, l1b;
                    split_bf16(c[0], h0a, l0a); split_bf16(c[1], h0b, l0b);
                    split_bf16(c[2], h1a, l1a); split_bf16(c[3], h1b, l1b);
                    __nv_bfloat162 ph0; ph0.x = h0a; ph0.y = h0b;
                    __nv_bfloat162 pl0; pl0.x = l0a; pl0.y = l0b;
                    __nv_bfloat162 ph1; ph1.x = h1a; ph1.y = h1b;
                    __nv_bfloat162 pl1; pl1.x = l1a; pl1.y = l1b;
                    *(__nv_bfloat162*)&YH[o0] = ph0;
                    *(__nv_bfloat162*)&YL[o0] = pl0;
                    *(__nv_bfloat162*)&YH[o1] = ph1;
                    *(__nv_bfloat162*)&YL[o1] = pl1;
                } else if (TCMODE == 3) {
                    const float sc = 0.08838834764831845f;   // 1/sqrt(128)
                    float* p0 = Cp + (size_t)m * ldc + nn;
                    float* p1 = Cp + (size_t)(m + 8) * ldc + nn;
                    *(float2*)p0 = make_float2(c[0] * sc, c[1] * sc);
                    *(float2*)p1 = make_float2(c[2] * sc, c[3] * sc);
                } else {
                    float* p0 = Cp + (size_t)m * ldc + nn;
                    float* p1 = Cp + (size_t)(m + 8) * ldc + nn;
                    if (TCMODE == 2 && R != nullptr) {
                        float2 rv0 = *(const float2*)(R + (size_t)m * ldc + nn);
                        float2 rv1 = *(const float2*)(R + (size_t)(m + 8) * ldc + nn);
                        *(float2*)p0 = make_float2(c[0] + rv0.x, c[1] + rv0.y);
                        *(float2*)p1 = make_float2(c[2] + rv1.x, c[3] + rv1.y);
                    } else {
                        *(float2*)p0 = make_float2(c[0], c[1]);
                        *(float2*)p1 = make_float2(c[2], c[3]);
                    }
                }
            }
        }
    }
}

// ---------------------------------------------------------------------------
// SwiGLU + bf16 split
// ---------------------------------------------------------------------------
__global__ void silu_mul_split(const float* __restrict__ h1,
                               const float* __restrict__ h2,
                               bf16* __restrict__ oh, bf16* __restrict__ ol, int n4)
{
    int i = blockIdx.x * blockDim.x + threadIdx.x;
    if (i >= n4) return;
    float4 a = ((const float4*)h1)[i];
    float4 b = ((const float4*)h2)[i];
    float r[4];
    r[0] = a.x / (1.0f + __expf(-a.x)) * b.x;
    r[1] = a.y / (1.0f + __expf(-a.y)) * b.y;
    r[2] = a.z / (1.0f + __expf(-a.z)) * b.z;
    r[3] = a.w / (1.0f + __expf(-a.w)) * b.w;
    #pragma unroll
    for (int j = 0; j < 4; j++) {
        bf16 hi, lo; split_bf16(r[j], hi, lo);
        oh[i*4 + j] = hi; ol[i*4 + j] = lo;
    }
}

// ---------------------------------------------------------------------------
// Launch
// ---------------------------------------------------------------------------
extern "C" void kernel_launch(void* const* d_in, const int* in_sizes, int n_in,
                              void* d_out, int out_size)
{
    const float* x      = (const float*)d_in[0];
    const float* attn_w = (const float*)d_in[1];
    const float* ff_w   = (const float*)d_in[2];
    const float* wq     = (const float*)d_in[3];
    const float* wk     = (const float*)d_in[4];
    const float* wv     = (const float*)d_in[5];
    const float* wo     = (const float*)d_in[6];
    const float* w1     = (const float*)d_in[7];
    const float* w2     = (const float*)d_in[8];
    const float* w3     = (const float*)d_in[9];
    float* out = (float*)d_out;

    float *q, *k, *v, *s, *h1f, *h2f;
    bf16 *ah, *al, *qh, *ql, *kh, *kl, *vth, *vtl, *ph, *pl, *yh, *yl, *hh, *hl;
    bf16 *wqkvh, *wqkvl, *woh, *wol, *w12h, *w12l, *w3h, *w3l;
    cudaGetSymbolAddress((void**)&q,   g_q);
    cudaGetSymbolAddress((void**)&k,   g_k);
    cudaGetSymbolAddress((void**)&v,   g_v);
    cudaGetSymbolAddress((void**)&s,   g_s);
    cudaGetSymbolAddress((void**)&h1f, g_h1f);
    cudaGetSymbolAddress((void**)&h2f, g_h2f);
    cudaGetSymbolAddress((void**)&ah,  g_ah);
    cudaGetSymbolAddress((void**)&al,  g_al);
    cudaGetSymbolAddress((void**)&qh,  g_qh);
    cudaGetSymbolAddress((void**)&ql,  g_ql);
    cudaGetSymbolAddress((void**)&kh,  g_kh);
    cudaGetSymbolAddress((void**)&kl,  g_kl);
    cudaGetSymbolAddress((void**)&vth, g_vth);
    cudaGetSymbolAddress((void**)&vtl, g_vtl);
    cudaGetSymbolAddress((void**)&ph,  g_ph);
    cudaGetSymbolAddress((void**)&pl,  g_pl);
    cudaGetSymbolAddress((void**)&yh,  g_yh);
    cudaGetSymbolAddress((void**)&yl,  g_yl);
    cudaGetSymbolAddress((void**)&hh,  g_hh);
    cudaGetSymbolAddress((void**)&hl,  g_hl);
    cudaGetSymbolAddress((void**)&wqkvh, g_wqkv_h);
    cudaGetSymbolAddress((void**)&wqkvl, g_wqkv_l);
    cudaGetSymbolAddress((void**)&woh,   g_wo_h);
    cudaGetSymbolAddress((void**)&wol,   g_wo_l);
    cudaGetSymbolAddress((void**)&w12h,  g_w12_h);
    cudaGetSymbolAddress((void**)&w12l,  g_w12_l);
    cudaGetSymbolAddress((void**)&w3h,   g_w3_h);
    cudaGetSymbolAddress((void**)&w3l,   g_w3_l);

    cudaFuncSetAttribute(tc_gemm<0>, cudaFuncAttributeMaxDynamicSharedMemorySize, TC_SMEM_BYTES);
    cudaFuncSetAttribute(tc_gemm<1>, cudaFuncAttributeMaxDynamicSharedMemorySize, TC_SMEM_BYTES);
    cudaFuncSetAttribute(tc_gemm<2>, cudaFuncAttributeMaxDynamicSharedMemorySize, TC_SMEM_BYTES);
    cudaFuncSetAttribute(tc_gemm<3>, cudaFuncAttributeMaxDynamicSharedMemorySize, TC_SMEM_BYTES);
    cudaFuncSetAttribute(tc_gemm<4>, cudaFuncAttributeMaxDynamicSharedMemorySize, TC_SMEM_BYTES);

    dim3 tb(32, 8);

    // Launch order puts tc_gemm<0> at index 5 so ncu (-s 5 -c 1) captures it.
    wsplit_t<<<dim3(DIM_/32, DIM_/32), tb>>>(wq, wqkvh, wqkvl, DIM_, DIM_, 0);     // 0
    wsplit_t<<<dim3(512/32,  DIM_/32), tb>>>(wk, wqkvh, wqkvl, DIM_, 512,  2048);  // 1
    wsplit_t<<<dim3(512/32,  DIM_/32), tb>>>(wv, wqkvh, wqkvl, DIM_, 512,  2560);  // 2
    rmsnorm_split<<<M_TOK, 256>>>(x, attn_w, ah, al);                               // 3
    wsplit_t<<<dim3(HID_/32, DIM_/32), tb>>>(w1, w12h, w12l, DIM_, HID_, 0);       // 4

    // 5: QKV (N = 3072)  <- ncu capture target
    tc_gemm<0><<<dim3(3072/128, M_TOK/128), 256, TC_SMEM_BYTES>>>(
        ah, al, wqkvh, wqkvl, q, k, v, nullptr, nullptr, nullptr, DIM_);

    wsplit_t<<<dim3(HID_/32, DIM_/32), tb>>>(w2, w12h, w12l, DIM_, HID_, HID_);    // 6
    wsplit_t<<<dim3(DIM_/32, DIM_/32), tb>>>(wo, woh, wol, DIM_, DIM_, 0);         // 7
    wsplit_t<<<dim3(DIM_/32, HID_/32), tb>>>(w3, w3h, w3l, HID_, DIM_, 0);         // 8

    {
        int tq = M_TOK * H_ * 64;
        rope_split<<<(tq + 255) / 256, 256>>>(q, qh, ql, H_, tq);                   // 9
        int tk = M_TOK * HKV_ * 64;
        rope_split<<<(tk + 255) / 256, 256>>>(k, kh, kl, HKV_, tk);                 // 10
    }
    vsplit_t<<<dim3(DH_/32, T_/32, B_*HKV_), tb>>>(v, vth, vtl);                    // 11

    // scores: S[z] = (Q K^T)/sqrt(DH), causal tiles skipped
    tc_gemm<3><<<dim3(T_/128, T_/128, B_*H_), 256, TC_SMEM_BYTES>>>(
        qh, ql, kh, kl, s, nullptr, nullptr, nullptr, nullptr, nullptr, DH_);       // 12

    softmax_split<<<B_*H_*T_, 128>>>(s, ph, pl);                                    // 13

    // PV: y = P V, output bf16 split
    tc_gemm<4><<<dim3(1, T_/128, B_*H_), 256, TC_SMEM_BYTES>>>(
        ph, pl, vth, vtl, nullptr, nullptr, nullptr, nullptr, yh, yl, T_);          // 14

    // out = x + y @ wo
    tc_gemm<2><<<dim3(DIM_/128, M_TOK/128), 256, TC_SMEM_BYTES>>>(
        yh, yl, woh, wol, out, nullptr, nullptr, x, nullptr, nullptr, DIM_);        // 15

    rmsnorm_split<<<M_TOK, 256>>>(out, ff_w, ah, al);                               // 16

    tc_gemm<1><<<dim3((2*HID_)/128, M_TOK/128), 256, TC_SMEM_BYTES>>>(
        ah, al, w12h, w12l, h1f, h2f, nullptr, nullptr, nullptr, nullptr, DIM_);    // 17

    {
        int n4 = (M_TOK * HID_) / 4;
        silu_mul_split<<<(n4 + 255) / 256, 256>>>(h1f, h2f, hh, hl, n4);            // 18
    }

    // out = out + (silu(h1)*h2) @ w3
    tc_gemm<2><<<dim3(DIM_/128, M_TOK/128), 256, TC_SMEM_BYTES>>>(
        hh, hl, w3h, w3l, out, nullptr, nullptr, out, nullptr, nullptr, HID_);      // 19
}